// round 2
// baseline (speedup 1.0000x reference)
#include <cuda_runtime.h>
#include <cstdint>

#define D_FEAT 128
#define MAX_NODES 65536
#define MAX_EDGES 1100000
#define SCAN_THREADS 1024

// ---------------- scratch (static device globals: allocation-free) ----------
__device__ int  g_count[MAX_NODES];
__device__ int  g_rowstart[MAX_NODES + 1];
__device__ int  g_cursor[MAX_NODES];
__device__ int2 g_slots[MAX_EDGES];    // {src, float_as_int(val)} per CSR slot

// ---------------------------------------------------------------------------
// 0) zero the histogram
// ---------------------------------------------------------------------------
__global__ void zero_count_kernel(int n_rows) {
    int i = blockIdx.x * blockDim.x + threadIdx.x;
    if (i < n_rows) g_count[i] = 0;
}

// ---------------------------------------------------------------------------
// 1) histogram of destination degrees
// ---------------------------------------------------------------------------
__global__ void hist_kernel(const int* __restrict__ dst, int n_edges) {
    int i = blockIdx.x * blockDim.x + threadIdx.x;
    if (i < n_edges) atomicAdd(&g_count[dst[i]], 1);
}

// ---------------------------------------------------------------------------
// 2) exclusive scan of counts -> rowstart & cursor (single block)
// ---------------------------------------------------------------------------
__global__ void scan_kernel(int n_rows) {
    __shared__ int sh[SCAN_THREADS];
    int t = threadIdx.x;
    int C = (n_rows + SCAN_THREADS - 1) / SCAN_THREADS;
    int beg = t * C;
    int end = min(n_rows, beg + C);

    int local = 0;
    for (int i = beg; i < end; ++i) local += g_count[i];

    sh[t] = local;
    __syncthreads();
    // Hillis-Steele inclusive scan over thread sums
    for (int off = 1; off < SCAN_THREADS; off <<= 1) {
        int v = (t >= off) ? sh[t - off] : 0;
        __syncthreads();
        sh[t] += v;
        __syncthreads();
    }
    int ex = sh[t] - local;   // exclusive prefix for this thread's chunk

    for (int i = beg; i < end; ++i) {
        g_rowstart[i] = ex;
        g_cursor[i]   = ex;
        ex += g_count[i];
    }
    if (t == SCAN_THREADS - 1) g_rowstart[n_rows] = sh[SCAN_THREADS - 1];
}

// ---------------------------------------------------------------------------
// 3) scatter edges into CSR slots
// ---------------------------------------------------------------------------
__global__ void fill_kernel(const int* __restrict__ src,
                            const int* __restrict__ dst,
                            const float* __restrict__ vals,
                            int n_edges) {
    int i = blockIdx.x * blockDim.x + threadIdx.x;
    if (i >= n_edges) return;
    int d   = dst[i];
    int pos = atomicAdd(&g_cursor[d], 1);
    g_slots[pos] = make_int2(src[i], __float_as_int(vals[i]));
}

// ---------------------------------------------------------------------------
// 4) warp-per-dst gather + accumulate + bias, single plain store
// ---------------------------------------------------------------------------
__global__ void gather_kernel(const float4* __restrict__ feat4,
                              const float4* __restrict__ bias4,
                              float4* __restrict__ out4,
                              int n_rows) {
    int gtid = blockIdx.x * blockDim.x + threadIdx.x;
    int node = gtid >> 5;
    int lane = gtid & 31;
    if (node >= n_rows) return;

    float4 acc = __ldg(&bias4[lane]);

    int beg = g_rowstart[node];
    int end = g_rowstart[node + 1];

    for (int e = beg; e < end; ++e) {
        int2 sv = __ldg(&g_slots[e]);           // broadcast across warp
        int   s = sv.x;
        float v = __int_as_float(sv.y);
        float4 f = __ldg(&feat4[(size_t)s * 32 + lane]);
        acc.x = fmaf(v, f.x, acc.x);
        acc.y = fmaf(v, f.y, acc.y);
        acc.z = fmaf(v, f.z, acc.z);
        acc.w = fmaf(v, f.w, acc.w);
    }

    out4[(size_t)node * 32 + lane] = acc;
}

// ---------------------------------------------------------------------------
// Fallback (R1 path) for shapes exceeding static scratch
// ---------------------------------------------------------------------------
__global__ void init_bias_kernel(float4* __restrict__ out,
                                 const float4* __restrict__ bias4,
                                 int total_vec4) {
    int idx = blockIdx.x * blockDim.x + threadIdx.x;
    if (idx >= total_vec4) return;
    out[idx] = __ldg(&bias4[idx & 31]);
}

__global__ void spmm_edge_kernel(const int* __restrict__ src,
                                 const int* __restrict__ dst,
                                 const float* __restrict__ vals,
                                 const float* __restrict__ feat,
                                 float* __restrict__ out,
                                 int n_edges) {
    int gtid = blockIdx.x * blockDim.x + threadIdx.x;
    int edge = gtid >> 5;
    int lane = gtid & 31;
    if (edge >= n_edges) return;

    int s = 0, d = 0;
    float v = 0.0f;
    if (lane == 0) { s = src[edge]; d = dst[edge]; v = vals[edge]; }
    s = __shfl_sync(0xffffffffu, s, 0);
    d = __shfl_sync(0xffffffffu, d, 0);
    v = __shfl_sync(0xffffffffu, v, 0);

    const float4* frow = reinterpret_cast<const float4*>(feat + (size_t)s * D_FEAT);
    float4 f = __ldg(&frow[lane]);
    float4 m = make_float4(f.x * v, f.y * v, f.z * v, f.w * v);

    float* orow = out + (size_t)d * D_FEAT + lane * 4;
    asm volatile("red.global.add.v4.f32 [%0], {%1, %2, %3, %4};"
                 :: "l"(orow), "f"(m.x), "f"(m.y), "f"(m.z), "f"(m.w)
                 : "memory");
}

// ---------------------------------------------------------------------------
// Launch
//   d_in[0] = edge_index (2*E int32: first E = src, next E = dst)
//   d_in[1] = edge_vals  (E fp32)
//   d_in[2] = features   (N*128 fp32)
//   d_in[3] = bias       (128 fp32)
// ---------------------------------------------------------------------------
extern "C" void kernel_launch(void* const* d_in, const int* in_sizes, int n_in,
                              void* d_out, int out_size) {
    const int*   edge_index = (const int*)d_in[0];
    const float* edge_vals  = (const float*)d_in[1];
    const float* features   = (const float*)d_in[2];
    const float* bias       = (const float*)d_in[3];
    float*       out        = (float*)d_out;

    int n_edges = in_sizes[1];
    int n_rows  = in_sizes[2] / D_FEAT;

    const int* src = edge_index;
    const int* dst = edge_index + n_edges;

    if (n_rows <= MAX_NODES && n_edges <= MAX_EDGES) {
        // ---- CSR build + gather path ----
        {
            int th = 256, bl = (n_rows + th - 1) / th;
            zero_count_kernel<<<bl, th>>>(n_rows);
        }
        {
            int th = 256, bl = (n_edges + th - 1) / th;
            hist_kernel<<<bl, th>>>(dst, n_edges);
        }
        scan_kernel<<<1, SCAN_THREADS>>>(n_rows);
        {
            int th = 256, bl = (n_edges + th - 1) / th;
            fill_kernel<<<bl, th>>>(src, dst, edge_vals, n_edges);
        }
        {
            int th = 256;
            long long total = (long long)n_rows * 32;
            int bl = (int)((total + th - 1) / th);
            gather_kernel<<<bl, th>>>((const float4*)features,
                                      (const float4*)bias,
                                      (float4*)out, n_rows);
        }
    } else {
        // ---- fallback: atomic scatter path ----
        {
            int total_vec4 = n_rows * (D_FEAT / 4);
            int th = 256, bl = (total_vec4 + th - 1) / th;
            init_bias_kernel<<<bl, th>>>((float4*)out, (const float4*)bias,
                                         total_vec4);
        }
        {
            int th = 256;
            long long total = (long long)n_edges * 32;
            int bl = (int)((total + th - 1) / th);
            spmm_edge_kernel<<<bl, th>>>(src, dst, edge_vals, features, out,
                                         n_edges);
        }
    }
}

// round 3
// speedup vs baseline: 2.6763x; 2.6763x over previous
#include <cuda_runtime.h>
#include <cstdint>

#define D_FEAT    128
#define MAX_NODES 65536
#define MAX_EDGES 1100000
#define BIN_CAP   96        // slots per node; Poisson(16) max-degree << 96

// ---------------- static device scratch (allocation-free) -------------------
__device__ int  g_cursor[MAX_NODES];
__device__ int2 g_slots[MAX_NODES * BIN_CAP];   // {src, float_as_int(val)}
__device__ int  g_over_cnt;
__device__ int  g_over_edges[MAX_EDGES];

// ---------------------------------------------------------------------------
// 1) zero per-node cursors + overflow counter
// ---------------------------------------------------------------------------
__global__ void zero_kernel(int n_rows) {
    int i = blockIdx.x * blockDim.x + threadIdx.x;
    if (i < n_rows) g_cursor[i] = 0;
    if (i == 0)     g_over_cnt = 0;
}

// ---------------------------------------------------------------------------
// 2) bin edges by dst into fixed-capacity slots (2 edges per thread for ILP)
// ---------------------------------------------------------------------------
__global__ void fill_kernel(const int*   __restrict__ src,
                            const int*   __restrict__ dst,
                            const float* __restrict__ vals,
                            int n_edges, int half)
{
    int i = blockIdx.x * blockDim.x + threadIdx.x;

    int e0 = i;
    int e1 = i + half;

    // edge 0
    if (e0 < half) {
        int d   = __ldg(&dst[e0]);
        int s   = __ldg(&src[e0]);
        float v = __ldg(&vals[e0]);
        int pos = atomicAdd(&g_cursor[d], 1);
        if (pos < BIN_CAP)
            g_slots[d * BIN_CAP + pos] = make_int2(s, __float_as_int(v));
        else
            g_over_edges[atomicAdd(&g_over_cnt, 1)] = e0;
    }
    // edge 1
    if (e1 < n_edges) {
        int d   = __ldg(&dst[e1]);
        int s   = __ldg(&src[e1]);
        float v = __ldg(&vals[e1]);
        int pos = atomicAdd(&g_cursor[d], 1);
        if (pos < BIN_CAP)
            g_slots[d * BIN_CAP + pos] = make_int2(s, __float_as_int(v));
        else
            g_over_edges[atomicAdd(&g_over_cnt, 1)] = e1;
    }
}

// ---------------------------------------------------------------------------
// 3) warp-per-node gather: acc = bias + sum(val * feat[src]); plain store
// ---------------------------------------------------------------------------
__global__ void gather_kernel(const float4* __restrict__ feat4,
                              const float4* __restrict__ bias4,
                              float4* __restrict__ out4,
                              int n_rows)
{
    int gtid = blockIdx.x * blockDim.x + threadIdx.x;
    int node = gtid >> 5;
    int lane = gtid & 31;
    if (node >= n_rows) return;

    float4 acc = __ldg(&bias4[lane]);

    int cnt = g_cursor[node];
    cnt = min(cnt, BIN_CAP);
    const int2* bin = g_slots + (size_t)node * BIN_CAP;

    int e = 0;
    // unrolled by 2: independent loads give the LSU MLP to hide L2 latency
    for (; e + 1 < cnt; e += 2) {
        int2 sv0 = __ldg(&bin[e]);
        int2 sv1 = __ldg(&bin[e + 1]);
        float4 f0 = __ldg(&feat4[(size_t)sv0.x * 32 + lane]);
        float4 f1 = __ldg(&feat4[(size_t)sv1.x * 32 + lane]);
        float v0 = __int_as_float(sv0.y);
        float v1 = __int_as_float(sv1.y);
        acc.x = fmaf(v0, f0.x, acc.x);
        acc.y = fmaf(v0, f0.y, acc.y);
        acc.z = fmaf(v0, f0.z, acc.z);
        acc.w = fmaf(v0, f0.w, acc.w);
        acc.x = fmaf(v1, f1.x, acc.x);
        acc.y = fmaf(v1, f1.y, acc.y);
        acc.z = fmaf(v1, f1.z, acc.z);
        acc.w = fmaf(v1, f1.w, acc.w);
    }
    if (e < cnt) {
        int2 sv = __ldg(&bin[e]);
        float4 f = __ldg(&feat4[(size_t)sv.x * 32 + lane]);
        float v = __int_as_float(sv.y);
        acc.x = fmaf(v, f.x, acc.x);
        acc.y = fmaf(v, f.y, acc.y);
        acc.z = fmaf(v, f.z, acc.z);
        acc.w = fmaf(v, f.w, acc.w);
    }

    out4[(size_t)node * 32 + lane] = acc;
}

// ---------------------------------------------------------------------------
// 4) overflow edges (empty in practice): grid-stride RED scatter on top of out
//    work item = (overflow_slot, lane); consecutive threads -> coalesced
// ---------------------------------------------------------------------------
__global__ void overflow_kernel(const int*   __restrict__ src,
                                const float* __restrict__ vals,
                                const float* __restrict__ feat,
                                float* __restrict__ out,
                                const int*   __restrict__ dst)
{
    int cnt = g_over_cnt;
    if (cnt == 0) return;
    long long total = (long long)cnt * 32;
    long long stride = (long long)gridDim.x * blockDim.x;
    for (long long w = blockIdx.x * (long long)blockDim.x + threadIdx.x;
         w < total; w += stride) {
        int slot = (int)(w >> 5);
        int lane = (int)(w & 31);
        int eid  = g_over_edges[slot];
        int s    = src[eid];
        int d    = dst[eid];
        float v  = vals[eid];
        const float4* frow = reinterpret_cast<const float4*>(feat + (size_t)s * D_FEAT);
        float4 f = __ldg(&frow[lane]);
        float4 m = make_float4(f.x * v, f.y * v, f.z * v, f.w * v);
        float* orow = out + (size_t)d * D_FEAT + lane * 4;
        asm volatile("red.global.add.v4.f32 [%0], {%1, %2, %3, %4};"
                     :: "l"(orow), "f"(m.x), "f"(m.y), "f"(m.z), "f"(m.w)
                     : "memory");
    }
}

// ---------------------------------------------------------------------------
// Fallback (R1 proven path) for shapes exceeding static scratch
// ---------------------------------------------------------------------------
__global__ void init_bias_kernel(float4* __restrict__ out,
                                 const float4* __restrict__ bias4,
                                 int total_vec4) {
    int idx = blockIdx.x * blockDim.x + threadIdx.x;
    if (idx >= total_vec4) return;
    out[idx] = __ldg(&bias4[idx & 31]);
}

__global__ void spmm_edge_kernel(const int* __restrict__ src,
                                 const int* __restrict__ dst,
                                 const float* __restrict__ vals,
                                 const float* __restrict__ feat,
                                 float* __restrict__ out,
                                 int n_edges) {
    int gtid = blockIdx.x * blockDim.x + threadIdx.x;
    int edge = gtid >> 5;
    int lane = gtid & 31;
    if (edge >= n_edges) return;

    int s = 0, d = 0;
    float v = 0.0f;
    if (lane == 0) { s = src[edge]; d = dst[edge]; v = vals[edge]; }
    s = __shfl_sync(0xffffffffu, s, 0);
    d = __shfl_sync(0xffffffffu, d, 0);
    v = __shfl_sync(0xffffffffu, v, 0);

    const float4* frow = reinterpret_cast<const float4*>(feat + (size_t)s * D_FEAT);
    float4 f = __ldg(&frow[lane]);
    float4 m = make_float4(f.x * v, f.y * v, f.z * v, f.w * v);

    float* orow = out + (size_t)d * D_FEAT + lane * 4;
    asm volatile("red.global.add.v4.f32 [%0], {%1, %2, %3, %4};"
                 :: "l"(orow), "f"(m.x), "f"(m.y), "f"(m.z), "f"(m.w)
                 : "memory");
}

// ---------------------------------------------------------------------------
// Launch.  d_in[0]=edge_index(2E i32: src then dst)  d_in[1]=edge_vals(E f32)
//          d_in[2]=features(N*128 f32)               d_in[3]=bias(128 f32)
// ---------------------------------------------------------------------------
extern "C" void kernel_launch(void* const* d_in, const int* in_sizes, int n_in,
                              void* d_out, int out_size)
{
    const int*   edge_index = (const int*)d_in[0];
    const float* edge_vals  = (const float*)d_in[1];
    const float* features   = (const float*)d_in[2];
    const float* bias       = (const float*)d_in[3];
    float*       out        = (float*)d_out;

    int n_edges = in_sizes[1];
    int n_rows  = in_sizes[2] / D_FEAT;

    const int* src = edge_index;
    const int* dst = edge_index + n_edges;

    if (n_rows <= MAX_NODES && n_edges <= MAX_EDGES) {
        {   // 1) zero cursors
            int th = 256, bl = (n_rows + th - 1) / th;
            zero_kernel<<<bl, th>>>(n_rows);
        }
        {   // 2) bin edges (2 per thread)
            int half = (n_edges + 1) / 2;
            int th = 256, bl = (half + th - 1) / th;
            fill_kernel<<<bl, th>>>(src, dst, edge_vals, n_edges, half);
        }
        {   // 3) gather (warp per node)
            int th = 256;
            long long total = (long long)n_rows * 32;
            int bl = (int)((total + th - 1) / th);
            gather_kernel<<<bl, th>>>((const float4*)features,
                                      (const float4*)bias,
                                      (float4*)out, n_rows);
        }
        {   // 4) overflow (expected empty)
            overflow_kernel<<<592, 256>>>(src, edge_vals, features, out, dst);
        }
    } else {
        {   // fallback: bias init + atomic scatter
            int total_vec4 = n_rows * (D_FEAT / 4);
            int th = 256, bl = (total_vec4 + th - 1) / th;
            init_bias_kernel<<<bl, th>>>((float4*)out, (const float4*)bias,
                                         total_vec4);
        }
        {
            int th = 256;
            long long total = (long long)n_edges * 32;
            int bl = (int)((total + th - 1) / th);
            spmm_edge_kernel<<<bl, th>>>(src, dst, edge_vals, features, out,
                                         n_edges);
        }
    }
}